// round 11
// baseline (speedup 1.0000x reference)
#include <cuda_runtime.h>
#include <math.h>

#define NMAX 50000
#define EMAX 800000

// ---------------- scratch (static device globals; no allocations) -------------
__device__ float g_XL1[NMAX * 128];
__device__ float g_XR1[NMAX * 128];
__device__ float g_H  [NMAX * 128];
__device__ float g_XL2[NMAX * 64];
__device__ float g_XR2[NMAX * 64];
__device__ float g_T  [NMAX * 128];
__device__ int   g_src[EMAX];
__device__ int   g_dst[EMAX];
__device__ int   g_csr[EMAX];
__device__ int   g_cnt[NMAX];
__device__ int   g_incl[NMAX];
__device__ int   g_rowptr[NMAX + 1];
__device__ int   g_cursor[NMAX + 2];
__device__ int   g_bsum[1024];
__device__ int   g_dummy[4];
__device__ int   g_is64;

// ---------------- zero + edge_index dtype detection ----------------------------
__global__ void zero_detect_kernel(const long long* __restrict__ ei, int E, int n) {
    int g = blockIdx.x * blockDim.x + threadIdx.x;
    if (g < n) g_cnt[g] = 0;
    if (g == 0) {
        int ok = 1;
        int m = E < 64 ? E : 64;
        for (int i = 0; i < m; i++) {
            long long v = ei[i];
            if (v < 0 || v >= NMAX) { ok = 0; break; }
        }
        g_is64 = ok;
    }
}

__global__ void hist_kernel(const void* __restrict__ eiv, int E, int n) {
    int e = blockIdx.x * blockDim.x + threadIdx.x;
    if (e >= E) return;
    int s, d;
    if (g_is64) {
        const long long* ei = (const long long*)eiv;
        s = (int)ei[e];
        d = (int)ei[(size_t)E + e];
    } else {
        const int* ei = (const int*)eiv;
        s = ei[e];
        d = ei[E + e];
    }
    if ((unsigned)s >= (unsigned)n || (unsigned)d >= (unsigned)n) { s = 0; d = 0; }
    g_src[e] = s;
    g_dst[e] = d;
    atomicAdd(&g_cnt[d], 1);
}

__global__ void scan1_kernel(int n, int phase) {
    __shared__ int sh[1024];
    const int* in = (phase == 0) ? g_cnt : g_bsum;
    int* incl     = (phase == 0) ? g_incl : g_bsum;
    int* bsum     = (phase == 0) ? g_bsum : g_dummy;
    int g = blockIdx.x * 1024 + threadIdx.x;
    int v = (g < n) ? in[g] : 0;
    sh[threadIdx.x] = v;
    __syncthreads();
    for (int off = 1; off < 1024; off <<= 1) {
        int t = (threadIdx.x >= off) ? sh[threadIdx.x - off] : 0;
        __syncthreads();
        sh[threadIdx.x] += t;
        __syncthreads();
    }
    if (g < n) incl[g] = sh[threadIdx.x];
    if (threadIdx.x == 1023) bsum[blockIdx.x] = sh[1023];
}

__global__ void scan3_kernel(int n) {
    int g = blockIdx.x * blockDim.x + threadIdx.x;
    if (g == 0) { g_rowptr[0] = 0; g_cursor[0] = 0; }
    if (g < n) {
        int b = g >> 10;
        int v = g_incl[g] + (b > 0 ? g_bsum[b - 1] : 0);
        g_rowptr[g + 1] = v;
        g_cursor[g + 1] = v;
    }
}

__global__ void scatter_kernel(int E) {
    int e = blockIdx.x * blockDim.x + threadIdx.x;
    if (e >= E) return;
    int d = g_dst[e];
    int pos = atomicAdd(&g_cursor[d], 1);
    g_csr[pos] = g_src[e];
}

// ---------------- tf32 tensor-core GEMM (double-buffered, paired smem) ---------
__device__ __forceinline__ unsigned f2tf32(float f) {
    unsigned u;
    asm("cvt.rna.tf32.f32 %0, %1;" : "=r"(u) : "f"(f));
    return u;
}

__device__ __forceinline__ void mma_tf32(float* c, unsigned a0, unsigned a1,
                                         unsigned a2, unsigned a3,
                                         unsigned b0, unsigned b1) {
    asm volatile(
        "mma.sync.aligned.m16n8k8.row.col.f32.tf32.tf32.f32 "
        "{%0,%1,%2,%3}, {%4,%5,%6,%7}, {%8,%9}, {%0,%1,%2,%3};\n"
        : "+f"(c[0]), "+f"(c[1]), "+f"(c[2]), "+f"(c[3])
        : "r"(a0), "r"(a1), "r"(a2), "r"(a3), "r"(b0), "r"(b1));
}

// out[N x M] = X[N x K] @ W[K x M] (+bias,relu), tf32 mma.
// 256 threads = 8 warps; warp tile 16 x 64; KC=16, double-buffered.
// Paired smem: entries are uint2 holding (k, k+4) operand pairs, indexed by
// p = ks*4 + t, so each mma operand pair is ONE conflict-free LDS.64:
//   Wsp[p][m], pad M+4  -> p-stride 8 banks; read lanes t*8+g*2 distinct.
//   Xsp[p][r], pad RB+4 -> same on reads; (2-way conflict on X stores only).
// xsel: 2 -> X = g_H, else Xp. osel: 0 g_XL1, 1 g_XR1, 3 g_XL2, 4 g_XR2, 5 g_T.
template <int K, int M, bool BIAS, bool RELU>
__global__ void mma_gemm_kernel(const float* __restrict__ Xp, const float* __restrict__ W,
                                const float* __restrict__ bias, int n, int xsel, int osel) {
    constexpr int KC  = 16;
    constexpr int WC  = M / 64;         // warps per col group (128->2, 64->1)
    constexpr int RB  = (8 / WC) * 16;  // rows per block (64 / 128)
    constexpr int NC  = K / KC;
    constexpr int Mp  = M + 4;          // uint2 stride for Wsp
    constexpr int Rp  = RB + 4;         // uint2 stride for Xsp
    constexpr int WI2 = M / 32;         // W uint2 per thread per chunk
    constexpr int XI2 = RB / 32;        // X uint2 per thread per chunk

    __shared__ uint2 Wsp[2][8 * Mp];
    __shared__ uint2 Xsp[2][8 * Rp];

    const float* X = (xsel == 2) ? g_H : Xp;
    float* out;
    switch (osel) {
        case 0: out = g_XL1; break;
        case 1: out = g_XR1; break;
        case 3: out = g_XL2; break;
        case 4: out = g_XR2; break;
        default: out = g_T;  break;
    }

    int tid  = threadIdx.x;
    int lane = tid & 31;
    int wid  = tid >> 5;
    int g    = lane >> 2;
    int t    = lane & 3;
    int wr   = wid / WC;
    int n0w  = (wid % WC) * 64;
    int row0 = blockIdx.x * RB;

    float2 wreg[WI2], xreg[XI2];

#define LDG_CHUNK(k0)                                                          \
    {                                                                          \
        _Pragma("unroll")                                                      \
        for (int u = 0; u < WI2; u++) {                                        \
            int i = tid + u * 256;                                             \
            int m = i & (M - 1), p = i / M;                                    \
            const float* wp = W + (size_t)((k0) + (p >> 2) * 8 + (p & 3)) * M + m; \
            wreg[u].x = wp[0];                                                 \
            wreg[u].y = wp[4 * M];                                             \
        }                                                                      \
        _Pragma("unroll")                                                      \
        for (int u = 0; u < XI2; u++) {                                        \
            int i = tid + u * 256;                                             \
            int p = i & 7, r = i >> 3;                                         \
            int row = row0 + r;                                                \
            const float* xp = X + (size_t)row * K + (k0) + (p >> 2) * 8 + (p & 3); \
            xreg[u].x = (row < n) ? xp[0] : 0.f;                               \
            xreg[u].y = (row < n) ? xp[4] : 0.f;                               \
        }                                                                      \
    }

#define STS_CHUNK(b)                                                           \
    {                                                                          \
        _Pragma("unroll")                                                      \
        for (int u = 0; u < WI2; u++) {                                        \
            int i = tid + u * 256;                                             \
            int m = i & (M - 1), p = i / M;                                    \
            Wsp[b][p * Mp + m] = make_uint2(f2tf32(wreg[u].x), f2tf32(wreg[u].y)); \
        }                                                                      \
        _Pragma("unroll")                                                      \
        for (int u = 0; u < XI2; u++) {                                        \
            int i = tid + u * 256;                                             \
            int p = i & 7, r = i >> 3;                                         \
            Xsp[b][p * Rp + r] = make_uint2(f2tf32(xreg[u].x), f2tf32(xreg[u].y)); \
        }                                                                      \
    }

    float acc[8][4];
#pragma unroll
    for (int i = 0; i < 8; i++)
#pragma unroll
        for (int j = 0; j < 4; j++) acc[i][j] = 0.f;

    LDG_CHUNK(0);
    STS_CHUNK(0);
    __syncthreads();

    int ar = wr * 16 + g;
    for (int c = 0; c < NC; c++) {
        if (c + 1 < NC) LDG_CHUNK((c + 1) * KC);
        int b = c & 1;
#pragma unroll
        for (int ks = 0; ks < 2; ks++) {
            int p = ks * 4 + t;
            uint2 a02 = Xsp[b][p * Rp + ar];
            uint2 a13 = Xsp[b][p * Rp + ar + 8];
#pragma unroll
            for (int nt = 0; nt < 8; nt++) {
                uint2 bb = Wsp[b][p * Mp + n0w + nt * 8 + g];
                mma_tf32(acc[nt], a02.x, a13.x, a02.y, a13.y, bb.x, bb.y);
            }
        }
        if (c + 1 < NC) STS_CHUNK((c + 1) & 1);
        __syncthreads();
    }

#undef LDG_CHUNK
#undef STS_CHUNK

    int r0 = row0 + wr * 16 + g;
    int r1 = r0 + 8;
#pragma unroll
    for (int nt = 0; nt < 8; nt++) {
        int c = n0w + nt * 8 + 2 * t;
        float bv0 = BIAS ? bias[c]     : 0.f;
        float bv1 = BIAS ? bias[c + 1] : 0.f;
        float v0 = acc[nt][0] + bv0, v1 = acc[nt][1] + bv1;
        float v2 = acc[nt][2] + bv0, v3 = acc[nt][3] + bv1;
        if constexpr (RELU) {
            v0 = fmaxf(v0, 0.f); v1 = fmaxf(v1, 0.f);
            v2 = fmaxf(v2, 0.f); v3 = fmaxf(v3, 0.f);
        }
        if (r0 < n) *(float2*)&out[(size_t)r0 * M + c] = make_float2(v0, v1);
        if (r1 < n) *(float2*)&out[(size_t)r1 * M + c] = make_float2(v2, v3);
    }
}

// ---------------- GATv2 aggregation: warp-per-node, fixed-reference softmax ----
template <int V>
__device__ __forceinline__ void ldv(float* d, const float* p) {
    if constexpr (V == 4) {
        float4 a = *(const float4*)p;
        d[0] = a.x; d[1] = a.y; d[2] = a.z; d[3] = a.w;
    } else {
        float2 a = *(const float2*)p;
        d[0] = a.x; d[1] = a.y;
    }
}

// LAYER 1: XL=g_XL1, XR=g_XR1, out=g_H; LAYER 2: XL=g_XL2, XR=g_XR2, out=param
template <int H, int C, bool RELU, int LAYER>
__global__ void gat_agg_kernel(const float* __restrict__ att, const float* __restrict__ bias,
                               float* __restrict__ outp, int n) {
    constexpr int D   = H * C;
    constexpr int V   = D / 32;
    constexpr int LPH = C / V;
    const float* XL = (LAYER == 1) ? g_XL1 : g_XL2;
    const float* XR = (LAYER == 1) ? g_XR1 : g_XR2;
    float* out      = (LAYER == 1) ? g_H   : outp;

    int w    = (blockIdx.x * blockDim.x + threadIdx.x) >> 5;
    int lane = threadIdx.x & 31;
    if (w >= n) return;

    float vr[V], vi[V], av[V], acc[V];
    ldv<V>(vr, XR + (size_t)w * D + lane * V);
    ldv<V>(vi, XL + (size_t)w * D + lane * V);
    ldv<V>(av, att + lane * V);

    float pself = 0.f;
#pragma unroll
    for (int v = 0; v < V; v++) {
        float e = vi[v] + vr[v];
        e = e > 0.f ? e : 0.2f * e;
        pself += e * av[v];
    }
#pragma unroll
    for (int off = 1; off < LPH; off <<= 1)
        pself += __shfl_xor_sync(0xffffffffu, pself, off);

    float s = 1.f;
#pragma unroll
    for (int v = 0; v < V; v++) acc[v] = vi[v];

    int beg = g_rowptr[w], end = g_rowptr[w + 1];
    for (int base = beg; base < end; base += 32) {
        int myidx = 0;
        if (base + lane < end) myidx = g_csr[base + lane];
        int cnt = min(32, end - base);
        for (int j = 0; j < cnt; j++) {
            int sidx = __shfl_sync(0xffffffffu, myidx, j);
            float xv[V];
            ldv<V>(xv, XL + (size_t)sidx * D + lane * V);
            float pl = 0.f;
#pragma unroll
            for (int v = 0; v < V; v++) {
                float e = xv[v] + vr[v];
                e = e > 0.f ? e : 0.2f * e;
                pl += e * av[v];
            }
#pragma unroll
            for (int off = 1; off < LPH; off <<= 1)
                pl += __shfl_xor_sync(0xffffffffu, pl, off);
            float ep = __expf(pl - pself);
            s += ep;
#pragma unroll
            for (int v = 0; v < V; v++) acc[v] += ep * xv[v];
        }
    }

    float inv = 1.f / s;
#pragma unroll
    for (int v = 0; v < V; v++) {
        float o = acc[v] * inv + bias[lane * V + v];
        if constexpr (RELU) o = fmaxf(o, 0.f);
        acc[v] = o;
    }
    float* op = out + (size_t)w * D + lane * V;
    if constexpr (V == 4) *(float4*)op = make_float4(acc[0], acc[1], acc[2], acc[3]);
    else                  *(float2*)op = make_float2(acc[0], acc[1]);
}

// ---------------- final tiny classifier layer: logits = g_T @ Wc2 + bc2 --------
__global__ void logits_kernel(const float* __restrict__ Wc2, const float* __restrict__ bc2,
                              float* __restrict__ lg, int n) {
    int w    = (blockIdx.x * blockDim.x + threadIdx.x) >> 5;
    int lane = threadIdx.x & 31;
    if (w >= n) return;
    float4 t = *(const float4*)&g_T[(size_t)w * 128 + lane * 4];
    int c = lane * 4;
    float l0 = t.x * Wc2[c * 2]           + t.y * Wc2[(c + 1) * 2]
             + t.z * Wc2[(c + 2) * 2]     + t.w * Wc2[(c + 3) * 2];
    float l1 = t.x * Wc2[c * 2 + 1]       + t.y * Wc2[(c + 1) * 2 + 1]
             + t.z * Wc2[(c + 2) * 2 + 1] + t.w * Wc2[(c + 3) * 2 + 1];
#pragma unroll
    for (int off = 16; off >= 1; off >>= 1) {
        l0 += __shfl_xor_sync(0xffffffffu, l0, off);
        l1 += __shfl_xor_sync(0xffffffffu, l1, off);
    }
    if (lane == 0) {
        lg[(size_t)w * 2 + 0] = l0 + bc2[0];
        lg[(size_t)w * 2 + 1] = l1 + bc2[1];
    }
}

// ---------------- launch --------------------------------------------------------
extern "C" void kernel_launch(void* const* d_in, const int* in_sizes, int n_in,
                              void* d_out, int out_size) {
    const float* x    = (const float*)d_in[0];
    const void*  ei   = d_in[1];
    const float* Wl1  = (const float*)d_in[3];
    const float* Wr1  = (const float*)d_in[4];
    const float* att1 = (const float*)d_in[5];
    const float* b1   = (const float*)d_in[6];
    const float* Wl2  = (const float*)d_in[7];
    const float* Wr2  = (const float*)d_in[8];
    const float* att2 = (const float*)d_in[9];
    const float* b2   = (const float*)d_in[10];
    const float* Wc1  = (const float*)d_in[15];
    const float* bc1  = (const float*)d_in[16];
    const float* Wc2  = (const float*)d_in[17];
    const float* bc2  = (const float*)d_in[18];

    int N = in_sizes[0] / 128;
    int E = in_sizes[1] / 2;
    float* out = (float*)d_out;
    float* emb = out;                       // [N, 64]
    float* lg  = out + (size_t)N * 64;      // [N, 2]

    int ablk = ((N * 32) + 255) / 256;
    int g64  = (N + 63) / 64;
    int g128 = (N + 127) / 128;
    int nblk = (N + 1023) / 1024;

    // CSR build interleaved with layer-1 GEMMs (GEMMs don't need the CSR; this
    // also puts a GEMM in the ncu capture window)
    zero_detect_kernel<<<(N + 255) / 256, 256>>>((const long long*)ei, E, N);         // 0
    hist_kernel<<<(E + 255) / 256, 256>>>(ei, E, N);                                  // 1
    mma_gemm_kernel<128, 128, false, false><<<g64, 256>>>(x, Wl1, nullptr, N, -1, 0); // 2
    mma_gemm_kernel<128, 128, false, false><<<g64, 256>>>(x, Wr1, nullptr, N, -1, 1); // 3
    scan1_kernel<<<nblk, 1024>>>(N, 0);                                               // 4
    scan1_kernel<<<1, 1024>>>(nblk, 1);                                               // 5
    scan3_kernel<<<(N + 255) / 256, 256>>>(N);                                        // 6
    scatter_kernel<<<(E + 255) / 256, 256>>>(E);                                      // 7

    // layer 1 aggregation
    gat_agg_kernel<8, 16, true, 1><<<ablk, 256>>>(att1, b1, nullptr, N);              // 8

    // layer 2
    mma_gemm_kernel<128, 64, false, false><<<g128, 256>>>(nullptr, Wl2, nullptr, N, 2, 3);
    mma_gemm_kernel<128, 64, false, false><<<g128, 256>>>(nullptr, Wr2, nullptr, N, 2, 4);
    gat_agg_kernel<1, 64, false, 2><<<ablk, 256>>>(att2, b2, emb, N);

    // classifier
    if (out_size >= N * 66) {
        mma_gemm_kernel<64, 128, true, true><<<g64, 256>>>(emb, Wc1, bc1, N, -1, 5);
        logits_kernel<<<ablk, 256>>>(Wc2, bc2, lg, N);
    }
}

// round 15
// speedup vs baseline: 1.0703x; 1.0703x over previous
#include <cuda_runtime.h>
#include <math.h>

#define NMAX 50000
#define EMAX 800000

// ---------------- scratch (static device globals; no allocations) -------------
__device__ float g_XL1[NMAX * 128];
__device__ float g_XR1[NMAX * 128];
__device__ float g_H  [NMAX * 128];
__device__ float g_XL2[NMAX * 64];
__device__ float g_XR2[NMAX * 64];
__device__ float g_T  [NMAX * 128];
__device__ int   g_src[EMAX];
__device__ int   g_dst[EMAX];
__device__ int   g_csr[EMAX];
__device__ int   g_cnt[NMAX];
__device__ int   g_incl[NMAX];
__device__ int   g_rowptr[NMAX + 1];
__device__ int   g_cursor[NMAX + 2];
__device__ int   g_bsum[1024];
__device__ int   g_dummy[4];
__device__ int   g_is64;

// ---------------- zero + edge_index dtype detection ----------------------------
__global__ void zero_detect_kernel(const long long* __restrict__ ei, int E, int n) {
    int g = blockIdx.x * blockDim.x + threadIdx.x;
    if (g < n) g_cnt[g] = 0;
    if (g == 0) {
        int ok = 1;
        int m = E < 64 ? E : 64;
        for (int i = 0; i < m; i++) {
            long long v = ei[i];
            if (v < 0 || v >= NMAX) { ok = 0; break; }
        }
        g_is64 = ok;
    }
}

__global__ void hist_kernel(const void* __restrict__ eiv, int E, int n) {
    int e = blockIdx.x * blockDim.x + threadIdx.x;
    if (e >= E) return;
    int s, d;
    if (g_is64) {
        const long long* ei = (const long long*)eiv;
        s = (int)ei[e];
        d = (int)ei[(size_t)E + e];
    } else {
        const int* ei = (const int*)eiv;
        s = ei[e];
        d = ei[E + e];
    }
    if ((unsigned)s >= (unsigned)n || (unsigned)d >= (unsigned)n) { s = 0; d = 0; }
    g_src[e] = s;
    g_dst[e] = d;
    atomicAdd(&g_cnt[d], 1);
}

__global__ void scan1_kernel(int n, int phase) {
    __shared__ int sh[1024];
    const int* in = (phase == 0) ? g_cnt : g_bsum;
    int* incl     = (phase == 0) ? g_incl : g_bsum;
    int* bsum     = (phase == 0) ? g_bsum : g_dummy;
    int g = blockIdx.x * 1024 + threadIdx.x;
    int v = (g < n) ? in[g] : 0;
    sh[threadIdx.x] = v;
    __syncthreads();
    for (int off = 1; off < 1024; off <<= 1) {
        int t = (threadIdx.x >= off) ? sh[threadIdx.x - off] : 0;
        __syncthreads();
        sh[threadIdx.x] += t;
        __syncthreads();
    }
    if (g < n) incl[g] = sh[threadIdx.x];
    if (threadIdx.x == 1023) bsum[blockIdx.x] = sh[1023];
}

__global__ void scan3_kernel(int n) {
    int g = blockIdx.x * blockDim.x + threadIdx.x;
    if (g == 0) { g_rowptr[0] = 0; g_cursor[0] = 0; }
    if (g < n) {
        int b = g >> 10;
        int v = g_incl[g] + (b > 0 ? g_bsum[b - 1] : 0);
        g_rowptr[g + 1] = v;
        g_cursor[g + 1] = v;
    }
}

__global__ void scatter_kernel(int E) {
    int e = blockIdx.x * blockDim.x + threadIdx.x;
    if (e >= E) return;
    int d = g_dst[e];
    int pos = atomicAdd(&g_cursor[d], 1);
    g_csr[pos] = g_src[e];
}

// ---------------- tf32 tensor-core GEMM (cp.async double-buffered) -------------
__device__ __forceinline__ void mma_tf32(float* c, unsigned a0, unsigned a1,
                                         unsigned a2, unsigned a3,
                                         unsigned b0, unsigned b1) {
    asm volatile(
        "mma.sync.aligned.m16n8k8.row.col.f32.tf32.tf32.f32 "
        "{%0,%1,%2,%3}, {%4,%5,%6,%7}, {%8,%9}, {%0,%1,%2,%3};\n"
        : "+f"(c[0]), "+f"(c[1]), "+f"(c[2]), "+f"(c[3])
        : "r"(a0), "r"(a1), "r"(a2), "r"(a3), "r"(b0), "r"(b1));
}

__device__ __forceinline__ void cp_async16(unsigned smem_addr, const void* gptr,
                                           int srcbytes) {
    asm volatile("cp.async.ca.shared.global [%0], [%1], 16, %2;\n"
                 :: "r"(smem_addr), "l"(gptr), "r"(srcbytes));
}

// RNA-round a raw fp32 bit pattern for tf32 consumption: the mma reads bits
// [31:13], and truncate(u + 0x1000) == cvt.rna.tf32(u) exactly (half-ULP added
// to the magnitude; carry propagates into the exponent; ties away from zero).
#define TF32RND(u) ((u) + 0x1000u)

// out[N x M] = X[N x K] @ W[K x M] (+bias,relu), tf32 mma.
// 256 threads = 8 warps; warp tile 16 x 64; KC=16 chunks; cp.async staging
// directly GMEM->SMEM; RNA rounding applied via +0x1000 on fragment load.
// Conflict-free smem: Xs stride 20 (g*20+t distinct mod 32), Ws stride M+8
// (8t+g distinct mod 32). Both rows 16B-aligned for cp.async.
// xsel: 2 -> X = g_H, else Xp. osel: 0 g_XL1, 1 g_XR1, 3 g_XL2, 4 g_XR2, 5 g_T.
template <int K, int M, bool BIAS, bool RELU>
__global__ void mma_gemm_kernel(const float* __restrict__ Xp, const float* __restrict__ W,
                                const float* __restrict__ bias, int n, int xsel, int osel) {
    constexpr int KC  = 16;
    constexpr int KCp = 20;             // X row stride (floats); 80B, 16B-aligned
    constexpr int Mp  = M + 8;          // W row stride (floats); 16B-aligned
    constexpr int WC  = M / 64;         // warps per col group (128->2, 64->1)
    constexpr int RB  = (8 / WC) * 16;  // rows per block (64 / 128)
    constexpr int NC  = K / KC;
    constexpr int WV  = KC * M / 4 / 256;  // W float4 per thread per chunk
    constexpr int XV  = RB * KC / 4 / 256; // X float4 per thread per chunk

    __shared__ unsigned Ws[2][KC * Mp];
    __shared__ unsigned Xs[2][RB * KCp];

    const float* X = (xsel == 2) ? g_H : Xp;
    float* out;
    switch (osel) {
        case 0: out = g_XL1; break;
        case 1: out = g_XR1; break;
        case 3: out = g_XL2; break;
        case 4: out = g_XR2; break;
        default: out = g_T;  break;
    }

    int tid  = threadIdx.x;
    int lane = tid & 31;
    int wid  = tid >> 5;
    int g    = lane >> 2;
    int t    = lane & 3;
    int wr   = wid / WC;
    int n0w  = (wid % WC) * 64;
    int row0 = blockIdx.x * RB;

    unsigned wsb[2], xsb[2];
    wsb[0] = (unsigned)__cvta_generic_to_shared(&Ws[0][0]);
    wsb[1] = (unsigned)__cvta_generic_to_shared(&Ws[1][0]);
    xsb[0] = (unsigned)__cvta_generic_to_shared(&Xs[0][0]);
    xsb[1] = (unsigned)__cvta_generic_to_shared(&Xs[1][0]);

#define ISSUE_CHUNK(k0, b)                                                     \
    {                                                                          \
        _Pragma("unroll")                                                      \
        for (int u = 0; u < WV; u++) {                                         \
            int i4 = tid + u * 256;              /* float4 index */            \
            int k = i4 / (M / 4), m4 = i4 - k * (M / 4);                       \
            cp_async16(wsb[b] + (k * Mp + m4 * 4) * 4,                         \
                       W + (size_t)((k0) + k) * M + m4 * 4, 16);               \
        }                                                                      \
        _Pragma("unroll")                                                      \
        for (int u = 0; u < XV; u++) {                                         \
            int i4 = tid + u * 256;                                            \
            int r = i4 >> 2, k4 = i4 & 3;                                      \
            int row = row0 + r;                                                \
            cp_async16(xsb[b] + (r * KCp + k4 * 4) * 4,                        \
                       X + (size_t)row * K + (k0) + k4 * 4,                    \
                       row < n ? 16 : 0);                                      \
        }                                                                      \
        asm volatile("cp.async.commit_group;\n");                              \
    }

    float acc[8][4];
#pragma unroll
    for (int i = 0; i < 8; i++)
#pragma unroll
        for (int j = 0; j < 4; j++) acc[i][j] = 0.f;

    ISSUE_CHUNK(0, 0);
    asm volatile("cp.async.wait_group 0;\n");
    __syncthreads();

    int ar = wr * 16 + g;
    for (int c = 0; c < NC; c++) {
        if (c + 1 < NC) ISSUE_CHUNK((c + 1) * KC, (c + 1) & 1);
        int b = c & 1;
#pragma unroll
        for (int ks = 0; ks < KC / 8; ks++) {
            int kk = ks * 8;
            unsigned a0 = TF32RND(Xs[b][ar * KCp + kk + t]);
            unsigned a1 = TF32RND(Xs[b][(ar + 8) * KCp + kk + t]);
            unsigned a2 = TF32RND(Xs[b][ar * KCp + kk + t + 4]);
            unsigned a3 = TF32RND(Xs[b][(ar + 8) * KCp + kk + t + 4]);
#pragma unroll
            for (int nt = 0; nt < 8; nt++) {
                unsigned b0 = TF32RND(Ws[b][(kk + t) * Mp + n0w + nt * 8 + g]);
                unsigned b1 = TF32RND(Ws[b][(kk + t + 4) * Mp + n0w + nt * 8 + g]);
                mma_tf32(acc[nt], a0, a1, a2, a3, b0, b1);
            }
        }
        if (c + 1 < NC) asm volatile("cp.async.wait_group 0;\n");
        __syncthreads();
    }

#undef ISSUE_CHUNK

    int r0 = row0 + wr * 16 + g;
    int r1 = r0 + 8;
#pragma unroll
    for (int nt = 0; nt < 8; nt++) {
        int c = n0w + nt * 8 + 2 * t;
        float bv0 = BIAS ? bias[c]     : 0.f;
        float bv1 = BIAS ? bias[c + 1] : 0.f;
        float v0 = acc[nt][0] + bv0, v1 = acc[nt][1] + bv1;
        float v2 = acc[nt][2] + bv0, v3 = acc[nt][3] + bv1;
        if constexpr (RELU) {
            v0 = fmaxf(v0, 0.f); v1 = fmaxf(v1, 0.f);
            v2 = fmaxf(v2, 0.f); v3 = fmaxf(v3, 0.f);
        }
        if (r0 < n) *(float2*)&out[(size_t)r0 * M + c] = make_float2(v0, v1);
        if (r1 < n) *(float2*)&out[(size_t)r1 * M + c] = make_float2(v2, v3);
    }
}

// ---------------- GATv2 aggregation: warp-per-node, fixed-reference softmax ----
template <int V>
__device__ __forceinline__ void ldv(float* d, const float* p) {
    if constexpr (V == 4) {
        float4 a = *(const float4*)p;
        d[0] = a.x; d[1] = a.y; d[2] = a.z; d[3] = a.w;
    } else {
        float2 a = *(const float2*)p;
        d[0] = a.x; d[1] = a.y;
    }
}

// LAYER 1: XL=g_XL1, XR=g_XR1, out=g_H; LAYER 2: XL=g_XL2, XR=g_XR2, out=param
template <int H, int C, bool RELU, int LAYER>
__global__ void gat_agg_kernel(const float* __restrict__ att, const float* __restrict__ bias,
                               float* __restrict__ outp, int n) {
    constexpr int D   = H * C;
    constexpr int V   = D / 32;
    constexpr int LPH = C / V;
    const float* XL = (LAYER == 1) ? g_XL1 : g_XL2;
    const float* XR = (LAYER == 1) ? g_XR1 : g_XR2;
    float* out      = (LAYER == 1) ? g_H   : outp;

    int w    = (blockIdx.x * blockDim.x + threadIdx.x) >> 5;
    int lane = threadIdx.x & 31;
    if (w >= n) return;

    float vr[V], vi[V], av[V], acc[V];
    ldv<V>(vr, XR + (size_t)w * D + lane * V);
    ldv<V>(vi, XL + (size_t)w * D + lane * V);
    ldv<V>(av, att + lane * V);

    float pself = 0.f;
#pragma unroll
    for (int v = 0; v < V; v++) {
        float e = vi[v] + vr[v];
        e = e > 0.f ? e : 0.2f * e;
        pself += e * av[v];
    }
#pragma unroll
    for (int off = 1; off < LPH; off <<= 1)
        pself += __shfl_xor_sync(0xffffffffu, pself, off);

    float s = 1.f;
#pragma unroll
    for (int v = 0; v < V; v++) acc[v] = vi[v];

    int beg = g_rowptr[w], end = g_rowptr[w + 1];
    for (int base = beg; base < end; base += 32) {
        int myidx = 0;
        if (base + lane < end) myidx = g_csr[base + lane];
        int cnt = min(32, end - base);
        for (int j = 0; j < cnt; j++) {
            int sidx = __shfl_sync(0xffffffffu, myidx, j);
            float xv[V];
            ldv<V>(xv, XL + (size_t)sidx * D + lane * V);
            float pl = 0.f;
#pragma unroll
            for (int v = 0; v < V; v++) {
                float e = xv[v] + vr[v];
                e = e > 0.f ? e : 0.2f * e;
                pl += e * av[v];
            }
#pragma unroll
            for (int off = 1; off < LPH; off <<= 1)
                pl += __shfl_xor_sync(0xffffffffu, pl, off);
            float ep = __expf(pl - pself);
            s += ep;
#pragma unroll
            for (int v = 0; v < V; v++) acc[v] += ep * xv[v];
        }
    }

    float inv = 1.f / s;
#pragma unroll
    for (int v = 0; v < V; v++) {
        float o = acc[v] * inv + bias[lane * V + v];
        if constexpr (RELU) o = fmaxf(o, 0.f);
        acc[v] = o;
    }
    float* op = out + (size_t)w * D + lane * V;
    if constexpr (V == 4) *(float4*)op = make_float4(acc[0], acc[1], acc[2], acc[3]);
    else                  *(float2*)op = make_float2(acc[0], acc[1]);
}

// ---------------- final tiny classifier layer: logits = g_T @ Wc2 + bc2 --------
__global__ void logits_kernel(const float* __restrict__ Wc2, const float* __restrict__ bc2,
                              float* __restrict__ lg, int n) {
    int w    = (blockIdx.x * blockDim.x + threadIdx.x) >> 5;
    int lane = threadIdx.x & 31;
    if (w >= n) return;
    float4 t = *(const float4*)&g_T[(size_t)w * 128 + lane * 4];
    int c = lane * 4;
    float l0 = t.x * Wc2[c * 2]           + t.y * Wc2[(c + 1) * 2]
             + t.z * Wc2[(c + 2) * 2]     + t.w * Wc2[(c + 3) * 2];
    float l1 = t.x * Wc2[c * 2 + 1]       + t.y * Wc2[(c + 1) * 2 + 1]
             + t.z * Wc2[(c + 2) * 2 + 1] + t.w * Wc2[(c + 3) * 2 + 1];
#pragma unroll
    for (int off = 16; off >= 1; off >>= 1) {
        l0 += __shfl_xor_sync(0xffffffffu, l0, off);
        l1 += __shfl_xor_sync(0xffffffffu, l1, off);
    }
    if (lane == 0) {
        lg[(size_t)w * 2 + 0] = l0 + bc2[0];
        lg[(size_t)w * 2 + 1] = l1 + bc2[1];
    }
}

// ---------------- launch --------------------------------------------------------
extern "C" void kernel_launch(void* const* d_in, const int* in_sizes, int n_in,
                              void* d_out, int out_size) {
    const float* x    = (const float*)d_in[0];
    const void*  ei   = d_in[1];
    const float* Wl1  = (const float*)d_in[3];
    const float* Wr1  = (const float*)d_in[4];
    const float* att1 = (const float*)d_in[5];
    const float* b1   = (const float*)d_in[6];
    const float* Wl2  = (const float*)d_in[7];
    const float* Wr2  = (const float*)d_in[8];
    const float* att2 = (const float*)d_in[9];
    const float* b2   = (const float*)d_in[10];
    const float* Wc1  = (const float*)d_in[15];
    const float* bc1  = (const float*)d_in[16];
    const float* Wc2  = (const float*)d_in[17];
    const float* bc2  = (const float*)d_in[18];

    int N = in_sizes[0] / 128;
    int E = in_sizes[1] / 2;
    float* out = (float*)d_out;
    float* emb = out;                       // [N, 64]
    float* lg  = out + (size_t)N * 64;      // [N, 2]

    int ablk = ((N * 32) + 255) / 256;
    int g64  = (N + 63) / 64;
    int g128 = (N + 127) / 128;
    int nblk = (N + 1023) / 1024;

    // CSR build interleaved with layer-1 GEMMs (GEMMs don't need the CSR; this
    // also puts a GEMM in the ncu capture window)
    zero_detect_kernel<<<(N + 255) / 256, 256>>>((const long long*)ei, E, N);         // 0
    hist_kernel<<<(E + 255) / 256, 256>>>(ei, E, N);                                  // 1
    mma_gemm_kernel<128, 128, false, false><<<g64, 256>>>(x, Wl1, nullptr, N, -1, 0); // 2
    mma_gemm_kernel<128, 128, false, false><<<g64, 256>>>(x, Wr1, nullptr, N, -1, 1); // 3
    scan1_kernel<<<nblk, 1024>>>(N, 0);                                               // 4
    scan1_kernel<<<1, 1024>>>(nblk, 1);                                               // 5
    scan3_kernel<<<(N + 255) / 256, 256>>>(N);                                        // 6
    scatter_kernel<<<(E + 255) / 256, 256>>>(E);                                      // 7

    // layer 1 aggregation
    gat_agg_kernel<8, 16, true, 1><<<ablk, 256>>>(att1, b1, nullptr, N);              // 8

    // layer 2
    mma_gemm_kernel<128, 64, false, false><<<g128, 256>>>(nullptr, Wl2, nullptr, N, 2, 3);
    mma_gemm_kernel<128, 64, false, false><<<g128, 256>>>(nullptr, Wr2, nullptr, N, 2, 4);
    gat_agg_kernel<1, 64, false, 2><<<ablk, 256>>>(att2, b2, emb, N);

    // classifier
    if (out_size >= N * 66) {
        mma_gemm_kernel<64, 128, true, true><<<g64, 256>>>(emb, Wc1, bc1, N, -1, 5);
        logits_kernel<<<ablk, 256>>>(Wc2, bc2, lg, N);
    }
}

// round 16
// speedup vs baseline: 1.0800x; 1.0091x over previous
#include <cuda_runtime.h>
#include <math.h>

#define NMAX 50000
#define EMAX 800000

// ---------------- scratch (static device globals; no allocations) -------------
__device__ float g_XL1[NMAX * 128];
__device__ float g_XR1[NMAX * 128];
__device__ float g_H  [NMAX * 128];
__device__ float g_XL2[NMAX * 64];
__device__ float g_XR2[NMAX * 64];
__device__ float g_T  [NMAX * 128];
__device__ int   g_src[EMAX];
__device__ int   g_dst[EMAX];
__device__ int   g_csr[EMAX];
__device__ int   g_cnt[NMAX];
__device__ int   g_incl[NMAX];
__device__ int   g_rowptr[NMAX + 1];
__device__ int   g_cursor[NMAX + 2];
__device__ int   g_bsum[1024];
__device__ int   g_dummy[4];
__device__ int   g_is64;

// ---------------- zero + edge_index dtype detection ----------------------------
__global__ void zero_detect_kernel(const long long* __restrict__ ei, int E, int n) {
    int g = blockIdx.x * blockDim.x + threadIdx.x;
    if (g < n) g_cnt[g] = 0;
    if (g == 0) {
        int ok = 1;
        int m = E < 64 ? E : 64;
        for (int i = 0; i < m; i++) {
            long long v = ei[i];
            if (v < 0 || v >= NMAX) { ok = 0; break; }
        }
        g_is64 = ok;
    }
}

__global__ void hist_kernel(const void* __restrict__ eiv, int E, int n) {
    int e = blockIdx.x * blockDim.x + threadIdx.x;
    if (e >= E) return;
    int s, d;
    if (g_is64) {
        const long long* ei = (const long long*)eiv;
        s = (int)ei[e];
        d = (int)ei[(size_t)E + e];
    } else {
        const int* ei = (const int*)eiv;
        s = ei[e];
        d = ei[E + e];
    }
    if ((unsigned)s >= (unsigned)n || (unsigned)d >= (unsigned)n) { s = 0; d = 0; }
    g_src[e] = s;
    g_dst[e] = d;
    atomicAdd(&g_cnt[d], 1);
}

__global__ void scan1_kernel(int n, int phase) {
    __shared__ int sh[1024];
    const int* in = (phase == 0) ? g_cnt : g_bsum;
    int* incl     = (phase == 0) ? g_incl : g_bsum;
    int* bsum     = (phase == 0) ? g_bsum : g_dummy;
    int g = blockIdx.x * 1024 + threadIdx.x;
    int v = (g < n) ? in[g] : 0;
    sh[threadIdx.x] = v;
    __syncthreads();
    for (int off = 1; off < 1024; off <<= 1) {
        int t = (threadIdx.x >= off) ? sh[threadIdx.x - off] : 0;
        __syncthreads();
        sh[threadIdx.x] += t;
        __syncthreads();
    }
    if (g < n) incl[g] = sh[threadIdx.x];
    if (threadIdx.x == 1023) bsum[blockIdx.x] = sh[1023];
}

__global__ void scan3_kernel(int n) {
    int g = blockIdx.x * blockDim.x + threadIdx.x;
    if (g == 0) { g_rowptr[0] = 0; g_cursor[0] = 0; }
    if (g < n) {
        int b = g >> 10;
        int v = g_incl[g] + (b > 0 ? g_bsum[b - 1] : 0);
        g_rowptr[g + 1] = v;
        g_cursor[g + 1] = v;
    }
}

__global__ void scatter_kernel(int E) {
    int e = blockIdx.x * blockDim.x + threadIdx.x;
    if (e >= E) return;
    int d = g_dst[e];
    int pos = atomicAdd(&g_cursor[d], 1);
    g_csr[pos] = g_src[e];
}

// ---------------- tf32 tensor-core GEMM (cp.async triple-buffered) -------------
__device__ __forceinline__ void mma_tf32(float* c, unsigned a0, unsigned a1,
                                         unsigned a2, unsigned a3,
                                         unsigned b0, unsigned b1) {
    asm volatile(
        "mma.sync.aligned.m16n8k8.row.col.f32.tf32.tf32.f32 "
        "{%0,%1,%2,%3}, {%4,%5,%6,%7}, {%8,%9}, {%0,%1,%2,%3};\n"
        : "+f"(c[0]), "+f"(c[1]), "+f"(c[2]), "+f"(c[3])
        : "r"(a0), "r"(a1), "r"(a2), "r"(a3), "r"(b0), "r"(b1));
}

__device__ __forceinline__ void cp_async16(unsigned smem_addr, const void* gptr,
                                           int srcbytes) {
    asm volatile("cp.async.ca.shared.global [%0], [%1], 16, %2;\n"
                 :: "r"(smem_addr), "l"(gptr), "r"(srcbytes));
}

// RNA-round a raw fp32 bit pattern for tf32 consumption: the mma reads bits
// [31:13], and truncate(u + 0x1000) == cvt.rna.tf32(u) exactly (half-ULP added
// to the magnitude; carry propagates into the exponent; ties away from zero).
#define TF32RND(u) ((u) + 0x1000u)

// out[N x M] = X[N x K] @ W[K x M] (+bias,relu), tf32 mma.
// 256 threads = 8 warps; warp tile 16 x 64; KC=16 chunks; cp.async staging
// GMEM->SMEM with a 3-buffer pipeline (2 chunks in flight: wait_group 1 keeps
// chunk c+1 airborne while chunk c computes); RNA rounding via +0x1000 on
// fragment load.
// Conflict-free smem: Xs stride 20 (g*20+t distinct mod 32), Ws stride M+8
// (8t+g distinct mod 32). Both rows 16B-aligned for cp.async.
// Buffer-reuse safety: ISSUE(c+2) writes buf (c+2)%3 == (c-1)%3, whose last
// readers (compute(c-1), all warps) finished before this iteration's barrier.
// xsel: 2 -> X = g_H, else Xp. osel: 0 g_XL1, 1 g_XR1, 3 g_XL2, 4 g_XR2, 5 g_T.
template <int K, int M, bool BIAS, bool RELU>
__global__ void mma_gemm_kernel(const float* __restrict__ Xp, const float* __restrict__ W,
                                const float* __restrict__ bias, int n, int xsel, int osel) {
    constexpr int KC  = 16;
    constexpr int KCp = 20;             // X row stride (floats); 80B, 16B-aligned
    constexpr int Mp  = M + 8;          // W row stride (floats); 16B-aligned
    constexpr int WC  = M / 64;         // warps per col group (128->2, 64->1)
    constexpr int RB  = (8 / WC) * 16;  // rows per block (64 / 128)
    constexpr int NC  = K / KC;
    constexpr int WV  = KC * M / 4 / 256;  // W float4 per thread per chunk
    constexpr int XV  = RB * KC / 4 / 256; // X float4 per thread per chunk

    __shared__ unsigned Ws[3][KC * Mp];
    __shared__ unsigned Xs[3][RB * KCp];

    const float* X = (xsel == 2) ? g_H : Xp;
    float* out;
    switch (osel) {
        case 0: out = g_XL1; break;
        case 1: out = g_XR1; break;
        case 3: out = g_XL2; break;
        case 4: out = g_XR2; break;
        default: out = g_T;  break;
    }

    int tid  = threadIdx.x;
    int lane = tid & 31;
    int wid  = tid >> 5;
    int g    = lane >> 2;
    int t    = lane & 3;
    int wr   = wid / WC;
    int n0w  = (wid % WC) * 64;
    int row0 = blockIdx.x * RB;

    unsigned wsb[3], xsb[3];
#pragma unroll
    for (int b = 0; b < 3; b++) {
        wsb[b] = (unsigned)__cvta_generic_to_shared(&Ws[b][0]);
        xsb[b] = (unsigned)__cvta_generic_to_shared(&Xs[b][0]);
    }

#define ISSUE_CHUNK(k0, b)                                                     \
    {                                                                          \
        _Pragma("unroll")                                                      \
        for (int u = 0; u < WV; u++) {                                         \
            int i4 = tid + u * 256;              /* float4 index */            \
            int k = i4 / (M / 4), m4 = i4 - k * (M / 4);                       \
            cp_async16(wsb[b] + (k * Mp + m4 * 4) * 4,                         \
                       W + (size_t)((k0) + k) * M + m4 * 4, 16);               \
        }                                                                      \
        _Pragma("unroll")                                                      \
        for (int u = 0; u < XV; u++) {                                         \
            int i4 = tid + u * 256;                                            \
            int r = i4 >> 2, k4 = i4 & 3;                                      \
            int row = row0 + r;                                                \
            cp_async16(xsb[b] + (r * KCp + k4 * 4) * 4,                        \
                       X + (size_t)row * K + (k0) + k4 * 4,                    \
                       row < n ? 16 : 0);                                      \
        }                                                                      \
        asm volatile("cp.async.commit_group;\n");                              \
    }

    float acc[8][4];
#pragma unroll
    for (int i = 0; i < 8; i++)
#pragma unroll
        for (int j = 0; j < 4; j++) acc[i][j] = 0.f;

    ISSUE_CHUNK(0, 0);
    if (NC > 1) ISSUE_CHUNK(KC, 1);

    int ar = wr * 16 + g;
    for (int c = 0; c < NC; c++) {
        if (c + 1 < NC) asm volatile("cp.async.wait_group 1;\n");
        else            asm volatile("cp.async.wait_group 0;\n");
        __syncthreads();
        int b = c % 3;
#pragma unroll
        for (int ks = 0; ks < KC / 8; ks++) {
            int kk = ks * 8;
            unsigned a0 = TF32RND(Xs[b][ar * KCp + kk + t]);
            unsigned a1 = TF32RND(Xs[b][(ar + 8) * KCp + kk + t]);
            unsigned a2 = TF32RND(Xs[b][ar * KCp + kk + t + 4]);
            unsigned a3 = TF32RND(Xs[b][(ar + 8) * KCp + kk + t + 4]);
#pragma unroll
            for (int nt = 0; nt < 8; nt++) {
                unsigned b0 = TF32RND(Ws[b][(kk + t) * Mp + n0w + nt * 8 + g]);
                unsigned b1 = TF32RND(Ws[b][(kk + t + 4) * Mp + n0w + nt * 8 + g]);
                mma_tf32(acc[nt], a0, a1, a2, a3, b0, b1);
            }
        }
        if (c + 2 < NC) ISSUE_CHUNK((c + 2) * KC, (c + 2) % 3);
    }

#undef ISSUE_CHUNK

    int r0 = row0 + wr * 16 + g;
    int r1 = r0 + 8;
#pragma unroll
    for (int nt = 0; nt < 8; nt++) {
        int c = n0w + nt * 8 + 2 * t;
        float bv0 = BIAS ? bias[c]     : 0.f;
        float bv1 = BIAS ? bias[c + 1] : 0.f;
        float v0 = acc[nt][0] + bv0, v1 = acc[nt][1] + bv1;
        float v2 = acc[nt][2] + bv0, v3 = acc[nt][3] + bv1;
        if constexpr (RELU) {
            v0 = fmaxf(v0, 0.f); v1 = fmaxf(v1, 0.f);
            v2 = fmaxf(v2, 0.f); v3 = fmaxf(v3, 0.f);
        }
        if (r0 < n) *(float2*)&out[(size_t)r0 * M + c] = make_float2(v0, v1);
        if (r1 < n) *(float2*)&out[(size_t)r1 * M + c] = make_float2(v2, v3);
    }
}

// ---------------- GATv2 aggregation: warp-per-node, fixed-reference softmax ----
template <int V>
__device__ __forceinline__ void ldv(float* d, const float* p) {
    if constexpr (V == 4) {
        float4 a = *(const float4*)p;
        d[0] = a.x; d[1] = a.y; d[2] = a.z; d[3] = a.w;
    } else {
        float2 a = *(const float2*)p;
        d[0] = a.x; d[1] = a.y;
    }
}

// LAYER 1: XL=g_XL1, XR=g_XR1, out=g_H; LAYER 2: XL=g_XL2, XR=g_XR2, out=param
template <int H, int C, bool RELU, int LAYER>
__global__ void gat_agg_kernel(const float* __restrict__ att, const float* __restrict__ bias,
                               float* __restrict__ outp, int n) {
    constexpr int D   = H * C;
    constexpr int V   = D / 32;
    constexpr int LPH = C / V;
    const float* XL = (LAYER == 1) ? g_XL1 : g_XL2;
    const float* XR = (LAYER == 1) ? g_XR1 : g_XR2;
    float* out      = (LAYER == 1) ? g_H   : outp;

    int w    = (blockIdx.x * blockDim.x + threadIdx.x) >> 5;
    int lane = threadIdx.x & 31;
    if (w >= n) return;

    float vr[V], vi[V], av[V], acc[V];
    ldv<V>(vr, XR + (size_t)w * D + lane * V);
    ldv<V>(vi, XL + (size_t)w * D + lane * V);
    ldv<V>(av, att + lane * V);

    float pself = 0.f;
#pragma unroll
    for (int v = 0; v < V; v++) {
        float e = vi[v] + vr[v];
        e = e > 0.f ? e : 0.2f * e;
        pself += e * av[v];
    }
#pragma unroll
    for (int off = 1; off < LPH; off <<= 1)
        pself += __shfl_xor_sync(0xffffffffu, pself, off);

    float s = 1.f;
#pragma unroll
    for (int v = 0; v < V; v++) acc[v] = vi[v];

    int beg = g_rowptr[w], end = g_rowptr[w + 1];
    for (int base = beg; base < end; base += 32) {
        int myidx = 0;
        if (base + lane < end) myidx = g_csr[base + lane];
        int cnt = min(32, end - base);
        for (int j = 0; j < cnt; j++) {
            int sidx = __shfl_sync(0xffffffffu, myidx, j);
            float xv[V];
            ldv<V>(xv, XL + (size_t)sidx * D + lane * V);
            float pl = 0.f;
#pragma unroll
            for (int v = 0; v < V; v++) {
                float e = xv[v] + vr[v];
                e = e > 0.f ? e : 0.2f * e;
                pl += e * av[v];
            }
#pragma unroll
            for (int off = 1; off < LPH; off <<= 1)
                pl += __shfl_xor_sync(0xffffffffu, pl, off);
            float ep = __expf(pl - pself);
            s += ep;
#pragma unroll
            for (int v = 0; v < V; v++) acc[v] += ep * xv[v];
        }
    }

    float inv = 1.f / s;
#pragma unroll
    for (int v = 0; v < V; v++) {
        float o = acc[v] * inv + bias[lane * V + v];
        if constexpr (RELU) o = fmaxf(o, 0.f);
        acc[v] = o;
    }
    float* op = out + (size_t)w * D + lane * V;
    if constexpr (V == 4) *(float4*)op = make_float4(acc[0], acc[1], acc[2], acc[3]);
    else                  *(float2*)op = make_float2(acc[0], acc[1]);
}

// ---------------- final tiny classifier layer: logits = g_T @ Wc2 + bc2 --------
__global__ void logits_kernel(const float* __restrict__ Wc2, const float* __restrict__ bc2,
                              float* __restrict__ lg, int n) {
    int w    = (blockIdx.x * blockDim.x + threadIdx.x) >> 5;
    int lane = threadIdx.x & 31;
    if (w >= n) return;
    float4 t = *(const float4*)&g_T[(size_t)w * 128 + lane * 4];
    int c = lane * 4;
    float l0 = t.x * Wc2[c * 2]           + t.y * Wc2[(c + 1) * 2]
             + t.z * Wc2[(c + 2) * 2]     + t.w * Wc2[(c + 3) * 2];
    float l1 = t.x * Wc2[c * 2 + 1]       + t.y * Wc2[(c + 1) * 2 + 1]
             + t.z * Wc2[(c + 2) * 2 + 1] + t.w * Wc2[(c + 3) * 2 + 1];
#pragma unroll
    for (int off = 16; off >= 1; off >>= 1) {
        l0 += __shfl_xor_sync(0xffffffffu, l0, off);
        l1 += __shfl_xor_sync(0xffffffffu, l1, off);
    }
    if (lane == 0) {
        lg[(size_t)w * 2 + 0] = l0 + bc2[0];
        lg[(size_t)w * 2 + 1] = l1 + bc2[1];
    }
}

// ---------------- launch --------------------------------------------------------
extern "C" void kernel_launch(void* const* d_in, const int* in_sizes, int n_in,
                              void* d_out, int out_size) {
    const float* x    = (const float*)d_in[0];
    const void*  ei   = d_in[1];
    const float* Wl1  = (const float*)d_in[3];
    const float* Wr1  = (const float*)d_in[4];
    const float* att1 = (const float*)d_in[5];
    const float* b1   = (const float*)d_in[6];
    const float* Wl2  = (const float*)d_in[7];
    const float* Wr2  = (const float*)d_in[8];
    const float* att2 = (const float*)d_in[9];
    const float* b2   = (const float*)d_in[10];
    const float* Wc1  = (const float*)d_in[15];
    const float* bc1  = (const float*)d_in[16];
    const float* Wc2  = (const float*)d_in[17];
    const float* bc2  = (const float*)d_in[18];

    int N = in_sizes[0] / 128;
    int E = in_sizes[1] / 2;
    float* out = (float*)d_out;
    float* emb = out;                       // [N, 64]
    float* lg  = out + (size_t)N * 64;      // [N, 2]

    int ablk = ((N * 32) + 255) / 256;
    int g64  = (N + 63) / 64;
    int g128 = (N + 127) / 128;
    int nblk = (N + 1023) / 1024;

    // CSR build interleaved with layer-1 GEMMs (GEMMs don't need the CSR; this
    // also puts a GEMM in the ncu capture window)
    zero_detect_kernel<<<(N + 255) / 256, 256>>>((const long long*)ei, E, N);         // 0
    hist_kernel<<<(E + 255) / 256, 256>>>(ei, E, N);                                  // 1
    mma_gemm_kernel<128, 128, false, false><<<g64, 256>>>(x, Wl1, nullptr, N, -1, 0); // 2
    mma_gemm_kernel<128, 128, false, false><<<g64, 256>>>(x, Wr1, nullptr, N, -1, 1); // 3
    scan1_kernel<<<nblk, 1024>>>(N, 0);                                               // 4
    scan1_kernel<<<1, 1024>>>(nblk, 1);                                               // 5
    scan3_kernel<<<(N + 255) / 256, 256>>>(N);                                        // 6
    scatter_kernel<<<(E + 255) / 256, 256>>>(E);                                      // 7

    // layer 1 aggregation
    gat_agg_kernel<8, 16, true, 1><<<ablk, 256>>>(att1, b1, nullptr, N);              // 8

    // layer 2
    mma_gemm_kernel<128, 64, false, false><<<g128, 256>>>(nullptr, Wl2, nullptr, N, 2, 3);
    mma_gemm_kernel<128, 64, false, false><<<g128, 256>>>(nullptr, Wr2, nullptr, N, 2, 4);
    gat_agg_kernel<1, 64, false, 2><<<ablk, 256>>>(att2, b2, emb, N);

    // classifier
    if (out_size >= N * 66) {
        mma_gemm_kernel<64, 128, true, true><<<g64, 256>>>(emb, Wc1, bc1, N, -1, 5);
        logits_kernel<<<ablk, 256>>>(Wc2, bc2, lg, N);
    }
}